// round 2
// baseline (speedup 1.0000x reference)
#include <cuda_runtime.h>

#define B_ 8
#define N_ 1024
#define H_ 8
#define D_ 32

// QKV scratch: [s][b][h][n][d], s in {Q,K,V}
__device__ float g_qkv[3u * B_ * H_ * N_ * D_];  // 25.2 MB

// ---------------------------------------------------------------------------
// Kernel 1: QKV projection. out = x @ W + bias, scattered into g_qkv layout.
// x: [8192, 256] row-major, W: [256, 768] row-major, bias: [768]
// Block tile 64x64, 256 threads, 4x4 microtile, K chunks of 32.
// ---------------------------------------------------------------------------
__global__ __launch_bounds__(256) void qkv_gemm(
    const float* __restrict__ x, const float* __restrict__ W,
    const float* __restrict__ bias)
{
    __shared__ float As[64][33];
    __shared__ float Bs[32][64];

    const int tid = threadIdx.x;
    const int ty = tid >> 4, tx = tid & 15;
    const int rb = blockIdx.y * 64;   // row block (over B*N = 8192)
    const int cb = blockIdx.x * 64;   // col block (over 768)

    float c[4][4] = {};

    for (int k0 = 0; k0 < 256; k0 += 32) {
        #pragma unroll
        for (int i = tid; i < 64 * 32; i += 256) {
            int r = i >> 5, k = i & 31;
            As[r][k] = x[(rb + r) * 256 + k0 + k];
        }
        #pragma unroll
        for (int i = tid; i < 32 * 64; i += 256) {
            int k = i >> 6, cc = i & 63;
            Bs[k][cc] = W[(k0 + k) * 768 + cb + cc];
        }
        __syncthreads();

        #pragma unroll
        for (int kk = 0; kk < 32; kk++) {
            float a0 = As[ty * 4 + 0][kk];
            float a1 = As[ty * 4 + 1][kk];
            float a2 = As[ty * 4 + 2][kk];
            float a3 = As[ty * 4 + 3][kk];
            float4 bv = *(const float4*)&Bs[kk][tx * 4];
            c[0][0] += a0 * bv.x; c[0][1] += a0 * bv.y; c[0][2] += a0 * bv.z; c[0][3] += a0 * bv.w;
            c[1][0] += a1 * bv.x; c[1][1] += a1 * bv.y; c[1][2] += a1 * bv.z; c[1][3] += a1 * bv.w;
            c[2][0] += a2 * bv.x; c[2][1] += a2 * bv.y; c[2][2] += a2 * bv.z; c[2][3] += a2 * bv.w;
            c[3][0] += a3 * bv.x; c[3][1] += a3 * bv.y; c[3][2] += a3 * bv.z; c[3][3] += a3 * bv.w;
        }
        __syncthreads();
    }

    // Epilogue: column c0 -> (s, h, d); row r -> (b, n). Scatter float4.
    const int c0  = cb + tx * 4;
    const int s   = c0 >> 8;
    const int rem = c0 & 255;
    const int h   = rem >> 5;
    const int d   = rem & 31;   // multiple of 4
    float4 bb = *(const float4*)&bias[c0];
    #pragma unroll
    for (int j = 0; j < 4; j++) {
        int r = rb + ty * 4 + j;
        int b = r >> 10, n = r & 1023;
        float4 v = make_float4(c[j][0] + bb.x, c[j][1] + bb.y,
                               c[j][2] + bb.z, c[j][3] + bb.w);
        *(float4*)&g_qkv[((((s * 8 + b) * 8 + h) * 1024 + n) << 5) + d] = v;
    }
}

// ---------------------------------------------------------------------------
// Kernel 2: fused moire attention (flash-style online softmax).
// Block = (h, qtile, b), 256 threads, 64 queries x 64-key chunks.
// Moire identity: log(max(exp(t),1e-6)) == max(t, ln(1e-6)).
// mask is read as 4-byte words, tested for nonzero bits: correct for both
// int32 {0,1} and float32 {0.0,1.0} promotions of the reference bool array.
// ---------------------------------------------------------------------------
__global__ __launch_bounds__(256) void moire_attn(
    const float* __restrict__ adj, const unsigned int* __restrict__ mask,
    const float* __restrict__ shifts, const float* __restrict__ widths,
    const float* __restrict__ slw, float* __restrict__ out)
{
    __shared__ float Qs[64][36];
    __shared__ float Ks[64][36];
    __shared__ float Vs[64][36];
    __shared__ float Ps[64][68];

    const int h  = blockIdx.x;   // fastest: adjacent blocks share adj tile (L2 reuse)
    const int qt = blockIdx.y;
    const int b  = blockIdx.z;
    const int q0 = qt * 64;
    const int tid = threadIdx.x;
    const int ty = tid >> 4, tx = tid & 15;

    const float sh   = shifts[h];
    const float invw = 1.0f / fmaxf(widths[h], 0.5f);
    const float sl   = slw[h];

    const float* Qg = g_qkv + (size_t)(((0 * 8 + b) * 8 + h) * 1024) * 32;
    const float* Kg = g_qkv + (size_t)(((1 * 8 + b) * 8 + h) * 1024) * 32;
    const float* Vg = g_qkv + (size_t)(((2 * 8 + b) * 8 + h) * 1024) * 32;

    // Q tile, pre-scaled by 1/sqrt(32)
    #pragma unroll
    for (int i = tid; i < 64 * 32; i += 256) {
        int qi = i >> 5, d = i & 31;
        Qs[qi][d] = Qg[(q0 + qi) * 32 + d] * 0.17677669529663687f;
    }

    bool mq[4];
    #pragma unroll
    for (int j = 0; j < 4; j++) mq[j] = (mask[b * 1024 + q0 + ty * 4 + j] != 0u);

    float m[4], l[4], acc[4][2];
    #pragma unroll
    for (int j = 0; j < 4; j++) {
        m[j] = -1e30f; l[j] = 0.f; acc[j][0] = 0.f; acc[j][1] = 0.f;
    }

    for (int kb = 0; kb < 1024; kb += 64) {
        __syncthreads();  // previous PV done before overwriting tiles
        #pragma unroll
        for (int i = tid; i < 64 * 32; i += 256) {
            int kj = i >> 5, d = i & 31;
            Ks[kj][d] = Kg[(kb + kj) * 32 + d];
            Vs[kj][d] = Vg[(kb + kj) * 32 + d];
        }
        // adj prefetch (global, coalesced float4; L2-shared across heads)
        float4 adjv[4];
        {
            const float* ab = adj + (size_t)(b * 1024 + q0 + ty * 4) * 1024 + kb + tx * 4;
            #pragma unroll
            for (int j = 0; j < 4; j++) adjv[j] = *(const float4*)(ab + (size_t)j * 1024);
        }
        uint4 mk4 = *(const uint4*)(mask + b * 1024 + kb + tx * 4);
        __syncthreads();  // tiles ready

        // 4x4 score microtile: dot over D=32 with float4 shared loads
        float s[4][4] = {};
        #pragma unroll
        for (int dd = 0; dd < 32; dd += 4) {
            float4 qv[4], kv[4];
            #pragma unroll
            for (int j = 0; j < 4; j++) qv[j] = *(const float4*)&Qs[ty * 4 + j][dd];
            #pragma unroll
            for (int i = 0; i < 4; i++) kv[i] = *(const float4*)&Ks[tx * 4 + i][dd];
            #pragma unroll
            for (int j = 0; j < 4; j++)
                #pragma unroll
                for (int i = 0; i < 4; i++)
                    s[j][i] += qv[j].x * kv[i].x + qv[j].y * kv[i].y +
                               qv[j].z * kv[i].z + qv[j].w * kv[i].w;
        }

        // moire + self-loop + mask
        const bool mk[4] = {mk4.x != 0u, mk4.y != 0u, mk4.z != 0u, mk4.w != 0u};
        #pragma unroll
        for (int j = 0; j < 4; j++) {
            const float* av = (const float*)&adjv[j];
            #pragma unroll
            for (int i = 0; i < 4; i++) {
                float t = av[i] - sh;
                float val = s[j][i] + fmaxf(-t * t * invw, -13.815510557964274f);
                if (q0 + ty * 4 + j == kb + tx * 4 + i) val += sl;
                s[j][i] = (mq[j] && mk[i]) ? val : -1000000.0f;
            }
        }

        // online softmax (row groups = 16 lanes sharing ty)
        #pragma unroll
        for (int j = 0; j < 4; j++) {
            float cm = fmaxf(fmaxf(s[j][0], s[j][1]), fmaxf(s[j][2], s[j][3]));
            #pragma unroll
            for (int off = 8; off > 0; off >>= 1)
                cm = fmaxf(cm, __shfl_xor_sync(0xffffffffu, cm, off));
            float mn = fmaxf(m[j], cm);
            float alpha = __expf(m[j] - mn);
            m[j] = mn;
            float rs = 0.f;
            #pragma unroll
            for (int i = 0; i < 4; i++) { s[j][i] = __expf(s[j][i] - mn); rs += s[j][i]; }
            #pragma unroll
            for (int off = 8; off > 0; off >>= 1)
                rs += __shfl_xor_sync(0xffffffffu, rs, off);
            l[j] = l[j] * alpha + rs;
            acc[j][0] *= alpha; acc[j][1] *= alpha;
        }

        // stage P as [kj][qi] (float4 over qi)
        #pragma unroll
        for (int i = 0; i < 4; i++) {
            float4 p4 = make_float4(s[0][i], s[1][i], s[2][i], s[3][i]);
            *(float4*)&Ps[tx * 4 + i][ty * 4] = p4;
        }
        __syncthreads();  // P ready

        // PV: thread owns 4 queries x 2 dims (d = tx*2)
        #pragma unroll 8
        for (int kj = 0; kj < 64; kj++) {
            float4 p = *(const float4*)&Ps[kj][ty * 4];
            float2 v = *(const float2*)&Vs[kj][tx * 2];
            acc[0][0] += p.x * v.x; acc[0][1] += p.x * v.y;
            acc[1][0] += p.y * v.x; acc[1][1] += p.y * v.y;
            acc[2][0] += p.z * v.x; acc[2][1] += p.z * v.y;
            acc[3][0] += p.w * v.x; acc[3][1] += p.w * v.y;
        }
    }

    // epilogue: out[b, n, h*32 + d]
    #pragma unroll
    for (int j = 0; j < 4; j++) {
        float r = 1.f / l[j];
        float2 o = make_float2(acc[j][0] * r, acc[j][1] * r);
        *(float2*)&out[(size_t)(b * 1024 + q0 + ty * 4 + j) * 256 + h * 32 + tx * 2] = o;
    }
}

// ---------------------------------------------------------------------------
// Launch. Inputs: x, adj, mask, W_qkv, b_qkv, shifts, widths, self_loop_w
// ---------------------------------------------------------------------------
extern "C" void kernel_launch(void* const* d_in, const int* in_sizes, int n_in,
                              void* d_out, int out_size)
{
    const float*        x      = (const float*)d_in[0];
    const float*        adj    = (const float*)d_in[1];
    const unsigned int* mask   = (const unsigned int*)d_in[2];
    const float*        W_qkv  = (const float*)d_in[3];
    const float*        b_qkv  = (const float*)d_in[4];
    const float*        shifts = (const float*)d_in[5];
    const float*        widths = (const float*)d_in[6];
    const float*        slw    = (const float*)d_in[7];
    float*              out    = (float*)d_out;

    qkv_gemm<<<dim3(12, 128), 256>>>(x, W_qkv, b_qkv);
    moire_attn<<<dim3(8, 16, 8), 256>>>(adj, mask, shifts, widths, slw, out);
}

// round 3
// speedup vs baseline: 1.3803x; 1.3803x over previous
#include <cuda_runtime.h>

#define B_ 8
#define N_ 1024
#define H_ 8
#define D_ 32

// QKV scratch: [s][b][h][n][d], s in {Q,K,V}
__device__ float g_qkv[3u * B_ * H_ * N_ * D_];  // 25.2 MB

// ---------------------------------------------------------------------------
// Kernel 1: QKV projection. out = x @ W + bias, scattered into g_qkv layout.
// (at fp32 FMA floor already; unchanged)
// ---------------------------------------------------------------------------
__global__ __launch_bounds__(256) void qkv_gemm(
    const float* __restrict__ x, const float* __restrict__ W,
    const float* __restrict__ bias)
{
    __shared__ float As[64][33];
    __shared__ float Bs[32][64];

    const int tid = threadIdx.x;
    const int ty = tid >> 4, tx = tid & 15;
    const int rb = blockIdx.y * 64;
    const int cb = blockIdx.x * 64;

    float c[4][4] = {};

    for (int k0 = 0; k0 < 256; k0 += 32) {
        #pragma unroll
        for (int i = tid; i < 64 * 32; i += 256) {
            int r = i >> 5, k = i & 31;
            As[r][k] = x[(rb + r) * 256 + k0 + k];
        }
        #pragma unroll
        for (int i = tid; i < 32 * 64; i += 256) {
            int k = i >> 6, cc = i & 63;
            Bs[k][cc] = W[(k0 + k) * 768 + cb + cc];
        }
        __syncthreads();

        #pragma unroll
        for (int kk = 0; kk < 32; kk++) {
            float a0 = As[ty * 4 + 0][kk];
            float a1 = As[ty * 4 + 1][kk];
            float a2 = As[ty * 4 + 2][kk];
            float a3 = As[ty * 4 + 3][kk];
            float4 bv = *(const float4*)&Bs[kk][tx * 4];
            c[0][0] += a0 * bv.x; c[0][1] += a0 * bv.y; c[0][2] += a0 * bv.z; c[0][3] += a0 * bv.w;
            c[1][0] += a1 * bv.x; c[1][1] += a1 * bv.y; c[1][2] += a1 * bv.z; c[1][3] += a1 * bv.w;
            c[2][0] += a2 * bv.x; c[2][1] += a2 * bv.y; c[2][2] += a2 * bv.z; c[2][3] += a2 * bv.w;
            c[3][0] += a3 * bv.x; c[3][1] += a3 * bv.y; c[3][2] += a3 * bv.z; c[3][3] += a3 * bv.w;
        }
        __syncthreads();
    }

    const int c0  = cb + tx * 4;
    const int s   = c0 >> 8;
    const int rem = c0 & 255;
    const int h   = rem >> 5;
    const int d   = rem & 31;
    float4 bb = *(const float4*)&bias[c0];
    #pragma unroll
    for (int j = 0; j < 4; j++) {
        int r = rb + ty * 4 + j;
        int b = r >> 10, n = r & 1023;
        float4 v = make_float4(c[j][0] + bb.x, c[j][1] + bb.y,
                               c[j][2] + bb.z, c[j][3] + bb.w);
        *(float4*)&g_qkv[((((s * 8 + b) * 8 + h) * 1024 + n) << 5) + d] = v;
    }
}

// ---------------------------------------------------------------------------
// Kernel 2: fused moire attention (flash-style online softmax).
// k-lane mapping k = i*16 + tx  =>  lane stride = 1 row (36 floats, = bank+4)
// => conflict-free LDS.128 on K loads and STS.128 on P stores.
// ---------------------------------------------------------------------------
__global__ __launch_bounds__(256) void moire_attn(
    const float* __restrict__ adj, const unsigned int* __restrict__ mask,
    const float* __restrict__ shifts, const float* __restrict__ widths,
    const float* __restrict__ slw, float* __restrict__ out)
{
    __shared__ float Qs[64][36];
    __shared__ float Ks[64][36];
    __shared__ float Vs[64][36];
    __shared__ float Ps[64][68];

    const int h  = blockIdx.x;   // fastest: adjacent blocks share adj tile (L2 reuse)
    const int qt = blockIdx.y;
    const int b  = blockIdx.z;
    const int q0 = qt * 64;
    const int tid = threadIdx.x;
    const int ty = tid >> 4, tx = tid & 15;

    const float sh   = shifts[h];
    const float invw = 1.0f / fmaxf(widths[h], 0.5f);
    const float sl   = slw[h];

    const float* Qg = g_qkv + (size_t)(((0 * 8 + b) * 8 + h) * 1024) * 32;
    const float* Kg = g_qkv + (size_t)(((1 * 8 + b) * 8 + h) * 1024) * 32;
    const float* Vg = g_qkv + (size_t)(((2 * 8 + b) * 8 + h) * 1024) * 32;

    // Q tile (float4 staging), pre-scaled by 1/sqrt(32)
    #pragma unroll
    for (int i = tid; i < 64 * 8; i += 256) {
        int qi = i >> 3, d = (i & 7) * 4;
        float4 v = *(const float4*)&Qg[(q0 + qi) * 32 + d];
        v.x *= 0.17677669529663687f; v.y *= 0.17677669529663687f;
        v.z *= 0.17677669529663687f; v.w *= 0.17677669529663687f;
        *(float4*)&Qs[qi][d] = v;
    }

    bool mq[4];
    #pragma unroll
    for (int j = 0; j < 4; j++) mq[j] = (mask[b * 1024 + q0 + ty * 4 + j] != 0u);

    float m[4], l[4], acc[4][2];
    #pragma unroll
    for (int j = 0; j < 4; j++) {
        m[j] = -1e30f; l[j] = 0.f; acc[j][0] = 0.f; acc[j][1] = 0.f;
    }

    for (int kb = 0; kb < 1024; kb += 64) {
        __syncthreads();  // previous PV done before overwriting tiles
        // K/V staging, float4
        #pragma unroll
        for (int i = tid; i < 64 * 8; i += 256) {
            int kj = i >> 3, d = (i & 7) * 4;
            *(float4*)&Ks[kj][d] = *(const float4*)&Kg[(kb + kj) * 32 + d];
            *(float4*)&Vs[kj][d] = *(const float4*)&Vg[(kb + kj) * 32 + d];
        }
        // adj + mask prefetch for this thread's 4 k's: k = i*16 + tx (coalesced)
        float adjv[4][4];
        bool  mk[4];
        {
            const float* ab = adj + (size_t)(b * 1024 + q0 + ty * 4) * 1024 + kb + tx;
            #pragma unroll
            for (int i = 0; i < 4; i++) {
                #pragma unroll
                for (int j = 0; j < 4; j++)
                    adjv[j][i] = ab[(size_t)j * 1024 + i * 16];
                mk[i] = (mask[b * 1024 + kb + i * 16 + tx] != 0u);
            }
        }
        __syncthreads();  // tiles ready

        // 4x4 score microtile: dot over D=32, conflict-free K loads
        float s[4][4] = {};
        #pragma unroll
        for (int dd = 0; dd < 32; dd += 4) {
            float4 qv[4], kv[4];
            #pragma unroll
            for (int j = 0; j < 4; j++) qv[j] = *(const float4*)&Qs[ty * 4 + j][dd];
            #pragma unroll
            for (int i = 0; i < 4; i++) kv[i] = *(const float4*)&Ks[i * 16 + tx][dd];
            #pragma unroll
            for (int j = 0; j < 4; j++)
                #pragma unroll
                for (int i = 0; i < 4; i++)
                    s[j][i] += qv[j].x * kv[i].x + qv[j].y * kv[i].y +
                               qv[j].z * kv[i].z + qv[j].w * kv[i].w;
        }

        // moire + self-loop + mask
        #pragma unroll
        for (int j = 0; j < 4; j++) {
            #pragma unroll
            for (int i = 0; i < 4; i++) {
                float t = adjv[j][i] - sh;
                float val = s[j][i] + fmaxf(-t * t * invw, -13.815510557964274f);
                if (q0 + ty * 4 + j == kb + i * 16 + tx) val += sl;
                s[j][i] = (mq[j] && mk[i]) ? val : -1000000.0f;
            }
        }

        // online softmax (rows distributed over 16 tx lanes + 4 i regs)
        #pragma unroll
        for (int j = 0; j < 4; j++) {
            float cm = fmaxf(fmaxf(s[j][0], s[j][1]), fmaxf(s[j][2], s[j][3]));
            #pragma unroll
            for (int off = 8; off > 0; off >>= 1)
                cm = fmaxf(cm, __shfl_xor_sync(0xffffffffu, cm, off));
            float mn = fmaxf(m[j], cm);
            float alpha = __expf(m[j] - mn);
            m[j] = mn;
            float rs = 0.f;
            #pragma unroll
            for (int i = 0; i < 4; i++) { s[j][i] = __expf(s[j][i] - mn); rs += s[j][i]; }
            #pragma unroll
            for (int off = 8; off > 0; off >>= 1)
                rs += __shfl_xor_sync(0xffffffffu, rs, off);
            l[j] = l[j] * alpha + rs;
            acc[j][0] *= alpha; acc[j][1] *= alpha;
        }

        // stage P as [k][q] (conflict-free: lane stride = 1 row = 68 floats)
        #pragma unroll
        for (int i = 0; i < 4; i++) {
            float4 p4 = make_float4(s[0][i], s[1][i], s[2][i], s[3][i]);
            *(float4*)&Ps[i * 16 + tx][ty * 4] = p4;
        }
        __syncthreads();  // P ready

        // PV: thread owns 4 queries x 2 dims (d = tx*2)
        #pragma unroll 8
        for (int kj = 0; kj < 64; kj++) {
            float4 p = *(const float4*)&Ps[kj][ty * 4];
            float2 v = *(const float2*)&Vs[kj][tx * 2];
            acc[0][0] += p.x * v.x; acc[0][1] += p.x * v.y;
            acc[1][0] += p.y * v.x; acc[1][1] += p.y * v.y;
            acc[2][0] += p.z * v.x; acc[2][1] += p.z * v.y;
            acc[3][0] += p.w * v.x; acc[3][1] += p.w * v.y;
        }
    }

    // epilogue: out[b, n, h*32 + d]
    #pragma unroll
    for (int j = 0; j < 4; j++) {
        float r = 1.f / l[j];
        float2 o = make_float2(acc[j][0] * r, acc[j][1] * r);
        *(float2*)&out[(size_t)(b * 1024 + q0 + ty * 4 + j) * 256 + h * 32 + tx * 2] = o;
    }
}

// ---------------------------------------------------------------------------
// Launch. Inputs: x, adj, mask, W_qkv, b_qkv, shifts, widths, self_loop_w
// ---------------------------------------------------------------------------
extern "C" void kernel_launch(void* const* d_in, const int* in_sizes, int n_in,
                              void* d_out, int out_size)
{
    const float*        x      = (const float*)d_in[0];
    const float*        adj    = (const float*)d_in[1];
    const unsigned int* mask   = (const unsigned int*)d_in[2];
    const float*        W_qkv  = (const float*)d_in[3];
    const float*        b_qkv  = (const float*)d_in[4];
    const float*        shifts = (const float*)d_in[5];
    const float*        widths = (const float*)d_in[6];
    const float*        slw    = (const float*)d_in[7];
    float*              out    = (float*)d_out;

    qkv_gemm<<<dim3(12, 128), 256>>>(x, W_qkv, b_qkv);
    moire_attn<<<dim3(8, 16, 8), 256>>>(adj, mask, shifts, widths, slw, out);
}